// round 1
// baseline (speedup 1.0000x reference)
#include <cuda_runtime.h>
#include <math.h>

#define L_SEQ 32768
#define H_DIM 128
#define P_DIM 256
#define CHUNK 64
#define NCHUNK (L_SEQ / CHUNK)   // 512
#define PTILE 64

typedef unsigned long long u64;

// ---------- f32x2 packed-FMA helpers (sm_100a) ----------
__device__ __forceinline__ u64 pack2(float lo, float hi) {
    u64 r;
    asm("mov.b64 %0, {%1,%2};" : "=l"(r) : "f"(lo), "f"(hi));
    return r;
}
__device__ __forceinline__ float2 unpack2(u64 v) {
    float2 f;
    asm("mov.b64 {%0,%1}, %2;" : "=f"(f.x), "=f"(f.y) : "l"(v));
    return f;
}
__device__ __forceinline__ u64 fma2(u64 a, u64 b, u64 c) {
    u64 d;
    asm("fma.rn.f32x2 %0, %1, %2, %3;" : "=l"(d) : "l"(a), "l"(b), "l"(c));
    return d;
}

// ---------- scratch (static device memory; no allocations) ----------
__device__ float2 g_xloc[(size_t)L_SEQ * P_DIM];     // 64 MB: local-scan states
__device__ float2 g_Acum[(size_t)L_SEQ * P_DIM];     // 64 MB: within-chunk cumulative A
__device__ float2 g_Achunk[NCHUNK * P_DIM];          // per-chunk A product
__device__ float2 g_xend[NCHUNK * P_DIM];            // per-chunk local end state
__device__ float2 g_carry[NCHUNK * P_DIM];           // carry-in per chunk
__device__ float2 g_Bt[H_DIM * P_DIM];               // B transposed+interleaved: [h][p] = (Br,Bi)
__device__ float2 g_Ct[P_DIM * H_DIM];               // C transposed+interleaved: [p][h] = (Cr,Ci)

// ---------- K0: pack/transpose B and C ----------
__global__ void k0_transpose(const float* __restrict__ Br, const float* __restrict__ Bi,
                             const float* __restrict__ Cr, const float* __restrict__ Ci) {
    int idx = blockIdx.x * blockDim.x + threadIdx.x;
    if (idx < H_DIM * P_DIM) {
        int h = idx / P_DIM, p = idx % P_DIM;
        g_Bt[idx] = make_float2(Br[p * H_DIM + h], Bi[p * H_DIM + h]);   // B[p][h] -> Bt[h][p]
        int p2 = idx / H_DIM, h2 = idx % H_DIM;
        g_Ct[idx] = make_float2(Cr[h2 * P_DIM + p2], Ci[h2 * P_DIM + p2]); // C[h][p] -> Ct[p][h]
    }
}

// ---------- K1: Bu = u @ B^T (complex), gamma, local scan per 64-row chunk ----------
// Block: 64 L-rows x 64 P-cols, 256 threads. Grid: (P/64=4, L/64=512).
__global__ __launch_bounds__(256) void k1_gemm_scan(
    const float* __restrict__ u, const float* __restrict__ dts,
    const float* __restrict__ Lre, const float* __restrict__ Lim,
    const float* __restrict__ logstep) {
    __shared__ __align__(16) float  u_s[CHUNK * 64];   // [r][k], 16 KB
    __shared__ __align__(16) float2 b_s[64 * PTILE];   // [k][c], 32 KB
    float2* xs_s = b_s;   // alias after GEMM: Bu tile [r][c]
    float*  dt_s = u_s;   // alias after GEMM: dt[64]

    int tid = threadIdx.x;
    int tx = tid & 15, ty = tid >> 4;
    int l0 = blockIdx.y * CHUNK;
    int p0 = blockIdx.x * PTILE;

    u64 acc[4][4];
#pragma unroll
    for (int i = 0; i < 4; i++)
#pragma unroll
        for (int j = 0; j < 4; j++) acc[i][j] = 0ULL;   // (0.0f, 0.0f)

    // K over H in two halves of 64
    for (int kh = 0; kh < 2; kh++) {
        int h0 = kh * 64;
        if (kh) __syncthreads();
        // stage u tile: 64 rows x 64 k floats (coalesced, conflict-free)
#pragma unroll
        for (int e = 0; e < 4; e++) {
            int f4 = e * 256 + tid;          // 0..1023 float4s
            int r = f4 >> 4, kq = f4 & 15;
            *reinterpret_cast<float4*>(&u_s[r * 64 + kq * 4]) =
                *reinterpret_cast<const float4*>(&u[(size_t)(l0 + r) * H_DIM + h0 + kq * 4]);
        }
        // stage B tile: [k][c] 64x64 float2 (coalesced, conflict-free)
#pragma unroll
        for (int e = 0; e < 8; e++) {
            int f4 = e * 256 + tid;          // 0..2047 float4s (2 float2 each)
            int k = f4 >> 5, cq = f4 & 31;
            *reinterpret_cast<float4*>(&b_s[k * PTILE + cq * 2]) =
                *reinterpret_cast<const float4*>(&g_Bt[(h0 + k) * P_DIM + p0 + cq * 2]);
        }
        __syncthreads();
#pragma unroll 8
        for (int k = 0; k < 64; k++) {
            u64 ua[4], bv[4];
#pragma unroll
            for (int i = 0; i < 4; i++) {
                float a = u_s[(ty + 16 * i) * 64 + k];
                ua[i] = pack2(a, a);
            }
#pragma unroll
            for (int j = 0; j < 4; j++)
                bv[j] = *reinterpret_cast<const u64*>(&b_s[k * PTILE + tx + 16 * j]);
#pragma unroll
            for (int i = 0; i < 4; i++)
#pragma unroll
                for (int j = 0; j < 4; j++)
                    acc[i][j] = fma2(ua[i], bv[j], acc[i][j]);   // (Bu_re, Bu_im)
        }
    }
    __syncthreads();
    // write Bu tile into smem (alias of b_s), and dt into u_s alias
#pragma unroll
    for (int i = 0; i < 4; i++)
#pragma unroll
        for (int j = 0; j < 4; j++)
            xs_s[(ty + 16 * i) * PTILE + tx + 16 * j] = unpack2(acc[i][j]);
    if (tid < CHUNK) dt_s[tid] = dts[l0 + tid];
    __syncthreads();

    // serial local scan: one thread per p-column
    if (tid < PTILE) {
        int p = p0 + tid;
        float lre = Lre[p], lim = Lim[p];
        float step = expf(logstep[p]);
        float inv = 1.0f / (lre * lre + lim * lim);   // |Lambda| >= 0.5 always
        float xr = 0.f, xi = 0.f, Ar = 1.f, Ai = 0.f;
        int cIdx = blockIdx.y;
#pragma unroll 4
        for (int l = 0; l < CHUNK; l++) {
            float d = dt_s[l] * step;
            float e = expf(lre * d);
            float s, c;
            sincosf(lim * d, &s, &c);
            float ar = e * c, ai = e * s;
            // gamma = (a-1)/Lambda = ((ar-1)+i*ai)*(lre - i*lim)*inv
            float arm1 = ar - 1.0f;
            float gr = (arm1 * lre + ai * lim) * inv;
            float gi = (ai * lre - arm1 * lim) * inv;
            float2 bu = xs_s[l * PTILE + tid];
            float br  = gr * bu.x - gi * bu.y;
            float bi2 = gr * bu.y + gi * bu.x;
            // x = a*x + b
            float nxr = ar * xr - ai * xi + br;
            float nxi = ar * xi + ai * xr + bi2;
            xr = nxr; xi = nxi;
            // Acum *= a
            float nAr = ar * Ar - ai * Ai;
            float nAi = ar * Ai + ai * Ar;
            Ar = nAr; Ai = nAi;
            size_t g = (size_t)(l0 + l) * P_DIM + p;
            g_xloc[g] = make_float2(xr, xi);
            g_Acum[g] = make_float2(Ar, Ai);
        }
        g_Achunk[cIdx * P_DIM + p] = make_float2(Ar, Ai);
        g_xend[cIdx * P_DIM + p]  = make_float2(xr, xi);
    }
}

// ---------- K2: scan over chunk aggregates (serial per p, 256 threads) ----------
__global__ void k2_chunkscan() {
    int p = threadIdx.x;   // 256
    float gr = 0.f, gi = 0.f;
    g_carry[p] = make_float2(0.f, 0.f);
    for (int c = 1; c < NCHUNK; c++) {
        float2 A  = g_Achunk[(c - 1) * P_DIM + p];
        float2 xe = g_xend[(c - 1) * P_DIM + p];
        float nr = A.x * gr - A.y * gi + xe.x;
        float ni = A.x * gi + A.y * gr + xe.y;
        gr = nr; gi = ni;
        g_carry[c * P_DIM + p] = make_float2(gr, gi);
    }
}

// ---------- K3: fixup x = Acum*carry + xloc, then y = 2*Re(x @ C^T) + D*u ----------
// Block: one 64-row chunk x all 128 H. 256 threads. K=256 complex in 8 slices of 32.
__global__ __launch_bounds__(256) void k3_fixup_gemm(
    const float* __restrict__ u, const float* __restrict__ D, float* __restrict__ out) {
    __shared__ __align__(16) float2 x_s[CHUNK * 32];   // [r][k], 16 KB
    __shared__ __align__(16) float2 c_s[32 * H_DIM];   // [k][h], 32 KB
    int tid = threadIdx.x, tx = tid & 15, ty = tid >> 4;
    int chunk = blockIdx.x;
    int l0 = chunk * CHUNK;

    u64 acc[4][8];
#pragma unroll
    for (int i = 0; i < 4; i++)
#pragma unroll
        for (int j = 0; j < 8; j++) acc[i][j] = 0ULL;

    for (int kc = 0; kc < 8; kc++) {
        int p0 = kc * 32;
        if (kc) __syncthreads();
        // stage fixed-up x: 64 rows x 32 p
#pragma unroll
        for (int e = 0; e < 8; e++) {
            int idx = e * 256 + tid;
            int r = idx >> 5, k = idx & 31;
            int p = p0 + k;
            size_t g = (size_t)(l0 + r) * P_DIM + p;
            float2 A  = g_Acum[g];
            float2 xl = g_xloc[g];
            float2 cr = g_carry[chunk * P_DIM + p];
            float2 x;
            x.x = A.x * cr.x - A.y * cr.y + xl.x;
            x.y = A.x * cr.y + A.y * cr.x + xl.y;
            x_s[r * 32 + k] = x;
        }
        // stage C slice: [k][h] 32x128 float2
#pragma unroll
        for (int e = 0; e < 8; e++) {
            int f4 = e * 256 + tid;          // 0..2047 float4s
            int k = f4 >> 6, hq = f4 & 63;
            *reinterpret_cast<float4*>(&c_s[k * H_DIM + hq * 2]) =
                *reinterpret_cast<const float4*>(&g_Ct[(p0 + k) * H_DIM + hq * 2]);
        }
        __syncthreads();
#pragma unroll 4
        for (int k = 0; k < 32; k++) {
            u64 xv[4], cv[8];
#pragma unroll
            for (int i = 0; i < 4; i++)
                xv[i] = *reinterpret_cast<const u64*>(&x_s[(ty + 16 * i) * 32 + k]);
#pragma unroll
            for (int j = 0; j < 8; j++)
                cv[j] = *reinterpret_cast<const u64*>(&c_s[k * H_DIM + tx + 16 * j]);
#pragma unroll
            for (int i = 0; i < 4; i++)
#pragma unroll
                for (int j = 0; j < 8; j++)
                    acc[i][j] = fma2(xv[i], cv[j], acc[i][j]);   // (sum xr*Cr, sum xi*Ci)
        }
    }
    // epilogue: y = 2*(lane0 - lane1) + D*u
#pragma unroll
    for (int i = 0; i < 4; i++) {
        int l = l0 + ty + 16 * i;
#pragma unroll
        for (int j = 0; j < 8; j++) {
            int h = tx + 16 * j;
            float2 s = unpack2(acc[i][j]);
            out[(size_t)l * H_DIM + h] = 2.0f * (s.x - s.y) + D[h] * u[(size_t)l * H_DIM + h];
        }
    }
}

extern "C" void kernel_launch(void* const* d_in, const int* in_sizes, int n_in,
                              void* d_out, int out_size) {
    const float* u       = (const float*)d_in[0];
    const float* dts     = (const float*)d_in[1];
    const float* Lre     = (const float*)d_in[2];
    const float* Lim     = (const float*)d_in[3];
    const float* logstep = (const float*)d_in[4];
    const float* Br      = (const float*)d_in[5];
    const float* Bi      = (const float*)d_in[6];
    const float* Cr      = (const float*)d_in[7];
    const float* Ci      = (const float*)d_in[8];
    const float* D       = (const float*)d_in[9];
    float* out = (float*)d_out;

    k0_transpose<<<(H_DIM * P_DIM + 255) / 256, 256>>>(Br, Bi, Cr, Ci);
    dim3 g1(P_DIM / PTILE, L_SEQ / CHUNK);
    k1_gemm_scan<<<g1, 256>>>(u, dts, Lre, Lim, logstep);
    k2_chunkscan<<<1, 256>>>();
    k3_fixup_gemm<<<L_SEQ / CHUNK, 256>>>(u, D, out);
}

// round 2
// speedup vs baseline: 1.6732x; 1.6732x over previous
#include <cuda_runtime.h>
#include <math.h>

#define L_SEQ 32768
#define H_DIM 128
#define P_DIM 256
#define CHUNK 64
#define NCHUNK (L_SEQ / CHUNK)   // 512
#define PTILE 64

typedef unsigned long long u64;

// ---------- f32x2 packed-FMA helpers ----------
__device__ __forceinline__ u64 pack2(float lo, float hi) {
    u64 r;
    asm("mov.b64 %0, {%1,%2};" : "=l"(r) : "f"(lo), "f"(hi));
    return r;
}
__device__ __forceinline__ float2 unpack2(u64 v) {
    float2 f;
    asm("mov.b64 {%0,%1}, %2;" : "=f"(f.x), "=f"(f.y) : "l"(v));
    return f;
}
__device__ __forceinline__ u64 fma2(u64 a, u64 b, u64 c) {
    u64 d;
    asm("fma.rn.f32x2 %0, %1, %2, %3;" : "=l"(d) : "l"(a), "l"(b), "l"(c));
    return d;
}

// ---------- cp.async helpers ----------
__device__ __forceinline__ void cp16(void* dst, const void* src) {
    unsigned d = (unsigned)__cvta_generic_to_shared(dst);
    asm volatile("cp.async.cg.shared.global [%0], [%1], 16;" :: "r"(d), "l"(src));
}
__device__ __forceinline__ void cpcommit() {
    asm volatile("cp.async.commit_group;");
}
template <int N>
__device__ __forceinline__ void cpwait() {
    asm volatile("cp.async.wait_group %0;" :: "n"(N));
}

// ---------- scratch (static device memory; no allocations) ----------
__device__ __align__(16) float2 g_xloc[(size_t)L_SEQ * P_DIM];   // 64 MB
__device__ __align__(16) float2 g_Acum[(size_t)L_SEQ * P_DIM];   // 64 MB
__device__ __align__(16) float2 g_Achunk[NCHUNK * P_DIM];
__device__ __align__(16) float2 g_xend[NCHUNK * P_DIM];
__device__ __align__(16) float2 g_carry[NCHUNK * P_DIM];
__device__ __align__(16) float2 g_Bt[H_DIM * P_DIM];             // [h][p]=(Br,Bi)
__device__ __align__(16) float2 g_Ct[P_DIM * H_DIM];             // [p][h]=(Cr,Ci)

// ---------- K0: pack/transpose B and C ----------
__global__ void k0_transpose(const float* __restrict__ Br, const float* __restrict__ Bi,
                             const float* __restrict__ Cr, const float* __restrict__ Ci) {
    int idx = blockIdx.x * blockDim.x + threadIdx.x;
    if (idx < H_DIM * P_DIM) {
        int h = idx / P_DIM, p = idx % P_DIM;
        g_Bt[idx] = make_float2(Br[p * H_DIM + h], Bi[p * H_DIM + h]);
        int p2 = idx / H_DIM, h2 = idx % H_DIM;
        g_Ct[idx] = make_float2(Cr[h2 * P_DIM + p2], Ci[h2 * P_DIM + p2]);
    }
}

// ---------- K1: Bu = u @ B^T (complex), then 4-way-parallel local scan ----------
// Block: 64 L-rows x 64 P-cols, 256 threads. Grid: (4, 512).
// GEMM double-buffered over 4 K-slices of 32 (u via cp.async, B via cp.async).
__global__ __launch_bounds__(256, 2) void k1_gemm_scan(
    const float* __restrict__ u, const float* __restrict__ dts,
    const float* __restrict__ Lre, const float* __restrict__ Lim,
    const float* __restrict__ logstep) {
    __shared__ __align__(16) char smem[49152];
    float*  uBuf0 = (float*)smem;                     // 8 KB
    float*  uBuf1 = (float*)(smem + 8192);            // 8 KB
    float2* bBuf0 = (float2*)(smem + 16384);          // 16 KB
    float2* bBuf1 = (float2*)(smem + 32768);          // 16 KB
    // scan-phase aliases
    float2* Bu    = (float2*)smem;                    // 32 KB (64x64 f2)
    float*  dt_s  = (float*)(smem + 32768);           // 256 B
    float2* As_s  = (float2*)(smem + 33024);          // 2 KB (4 segs x 64 p)
    float2* xs_s2 = (float2*)(smem + 35072);          // 2 KB

    int tid = threadIdx.x;
    int tx = tid & 15, ty = tid >> 4;
    int l0 = blockIdx.y * CHUNK;
    int p0 = blockIdx.x * PTILE;

    u64 acc[4][4];
#pragma unroll
    for (int i = 0; i < 4; i++)
#pragma unroll
        for (int j = 0; j < 4; j++) acc[i][j] = 0ULL;

    // stage slice s (h0 = s*32) into buffer b
    auto stage = [&](int s, int b) {
        int h0 = s * 32;
        float*  ub = b ? uBuf1 : uBuf0;
        float2* bb = b ? bBuf1 : bBuf0;
#pragma unroll
        for (int e = 0; e < 2; e++) {                 // 512 float4 of u
            int idx = e * 256 + tid;
            int r = idx >> 3, q = idx & 7;            // 8 float4 per row of 32
            cp16(&ub[r * 32 + q * 4], &u[(size_t)(l0 + r) * H_DIM + h0 + q * 4]);
        }
#pragma unroll
        for (int e = 0; e < 4; e++) {                 // 1024 float4 of B
            int idx = e * 256 + tid;
            int kk = idx >> 5, q = idx & 31;          // 32 float4 per row of 64 f2
            cp16(&bb[kk * PTILE + q * 2], &g_Bt[(h0 + kk) * P_DIM + p0 + q * 2]);
        }
        cpcommit();
    };

    stage(0, 0);
    stage(1, 1);
#pragma unroll
    for (int s = 0; s < 4; s++) {
        if (s < 3) cpwait<1>(); else cpwait<0>();
        __syncthreads();
        const float*  ub = (s & 1) ? uBuf1 : uBuf0;
        const float2* bb = (s & 1) ? bBuf1 : bBuf0;
#pragma unroll 8
        for (int kk = 0; kk < 32; kk++) {
            u64 ua[4], bv[4];
#pragma unroll
            for (int i = 0; i < 4; i++) {
                float a = ub[(ty + 16 * i) * 32 + kk];
                ua[i] = pack2(a, a);
            }
#pragma unroll
            for (int j = 0; j < 4; j++)
                bv[j] = *reinterpret_cast<const u64*>(&bb[kk * PTILE + tx + 16 * j]);
#pragma unroll
            for (int i = 0; i < 4; i++)
#pragma unroll
                for (int j = 0; j < 4; j++)
                    acc[i][j] = fma2(ua[i], bv[j], acc[i][j]);
        }
        __syncthreads();
        if (s + 2 < 4) stage(s + 2, s & 1);
    }

    // write Bu tile + dt into smem
#pragma unroll
    for (int i = 0; i < 4; i++)
#pragma unroll
        for (int j = 0; j < 4; j++)
            Bu[(ty + 16 * i) * PTILE + tx + 16 * j] = unpack2(acc[i][j]);
    if (tid < CHUNK) dt_s[tid] = dts[l0 + tid];
    __syncthreads();

    // ---- parallel local scan: 64 p-columns x 4 segments of 16 steps ----
    int p   = tid & 63;
    int seg = tid >> 6;
    int gp  = p0 + p;
    int lb  = seg * 16;
    float lre = Lre[gp], lim = Lim[gp];
    float step = expf(logstep[gp]);
    float inv = 1.0f / (lre * lre + lim * lim);

    float xrA[16], xiA[16], ArA[16], AiA[16];
    {
        float xr = 0.f, xi = 0.f, Ar = 1.f, Ai = 0.f;
#pragma unroll
        for (int j = 0; j < 16; j++) {
            float d = dt_s[lb + j] * step;
            float ee = expf(lre * d);
            float sn, cs;
            sincosf(lim * d, &sn, &cs);
            float ar = ee * cs, ai = ee * sn;
            float arm1 = ar - 1.0f;
            float gr = (arm1 * lre + ai * lim) * inv;
            float gi = (ai * lre - arm1 * lim) * inv;
            float2 bu = Bu[(lb + j) * PTILE + p];
            float br  = gr * bu.x - gi * bu.y;
            float bi2 = gr * bu.y + gi * bu.x;
            float nxr = ar * xr - ai * xi + br;
            float nxi = ar * xi + ai * xr + bi2;
            xr = nxr; xi = nxi;
            float nAr = ar * Ar - ai * Ai;
            float nAi = ar * Ai + ai * Ar;
            Ar = nAr; Ai = nAi;
            xrA[j] = xr; xiA[j] = xi; ArA[j] = Ar; AiA[j] = Ai;
        }
        As_s[seg * 64 + p]  = make_float2(Ar, Ai);
        xs_s2[seg * 64 + p] = make_float2(xr, xi);
    }
    __syncthreads();

    // segment carry / prefix-A for this thread's segment (<=3 iterations)
    float cr = 0.f, ci = 0.f, pr = 1.f, pi = 0.f;
    for (int s = 0; s < seg; s++) {
        float2 A  = As_s[s * 64 + p];
        float2 xe = xs_s2[s * 64 + p];
        float ncr = A.x * cr - A.y * ci + xe.x;
        float nci = A.x * ci + A.y * cr + xe.y;
        cr = ncr; ci = nci;
        float npr = A.x * pr - A.y * pi;
        float npi = A.x * pi + A.y * pr;
        pr = npr; pi = npi;
    }

    float lastAr = 0.f, lastAi = 0.f, lastXr = 0.f, lastXi = 0.f;
#pragma unroll
    for (int j = 0; j < 16; j++) {
        float AgR = pr * ArA[j] - pi * AiA[j];
        float AgI = pr * AiA[j] + pi * ArA[j];
        float xgR = ArA[j] * cr - AiA[j] * ci + xrA[j];
        float xgI = ArA[j] * ci + AiA[j] * cr + xiA[j];
        size_t g = (size_t)(l0 + lb + j) * P_DIM + gp;
        g_xloc[g] = make_float2(xgR, xgI);
        g_Acum[g] = make_float2(AgR, AgI);
        if (j == 15) { lastAr = AgR; lastAi = AgI; lastXr = xgR; lastXi = xgI; }
    }
    if (seg == 3) {
        g_Achunk[blockIdx.y * P_DIM + gp] = make_float2(lastAr, lastAi);
        g_xend[blockIdx.y * P_DIM + gp]   = make_float2(lastXr, lastXi);
    }
}

// ---------- K2: scan over chunk aggregates, batch-of-8 register prefetch ----------
__global__ void k2_chunkscan() {
    int p = blockIdx.x * 32 + threadIdx.x;   // 8 blocks x 32 threads = 256 p
    float gr = 0.f, gi = 0.f;
    g_carry[p] = make_float2(0.f, 0.f);
    float2 A[8], X[8];
#pragma unroll
    for (int i = 0; i < 8; i++) {
        A[i] = g_Achunk[i * P_DIM + p];
        X[i] = g_xend[i * P_DIM + p];
    }
    for (int b = 0; b < NCHUNK; b += 8) {
        float2 An[8], Xn[8];
        if (b + 8 < NCHUNK) {
#pragma unroll
            for (int i = 0; i < 8; i++) {
                An[i] = g_Achunk[(b + 8 + i) * P_DIM + p];
                Xn[i] = g_xend[(b + 8 + i) * P_DIM + p];
            }
        }
#pragma unroll
        for (int i = 0; i < 8; i++) {
            int c = b + i;
            float nr = A[i].x * gr - A[i].y * gi + X[i].x;
            float ni = A[i].x * gi + A[i].y * gr + X[i].y;
            gr = nr; gi = ni;
            if (c + 1 < NCHUNK) g_carry[(c + 1) * P_DIM + p] = make_float2(gr, gi);
        }
#pragma unroll
        for (int i = 0; i < 8; i++) { A[i] = An[i]; X[i] = Xn[i]; }
    }
}

// ---------- K3: fixup + y = 2*Re(x @ C^T) + D*u, double-buffered ----------
// Block: 64 rows x 128 H, 256 threads. 16 K-slices of 16 p each.
__global__ __launch_bounds__(256, 2) void k3_fixup_gemm(
    const float* __restrict__ u, const float* __restrict__ D, float* __restrict__ out) {
    __shared__ __align__(16) char smem[49152];
    float2* xBuf0 = (float2*)smem;                    // 8 KB (64x16)
    float2* xBuf1 = (float2*)(smem + 8192);           // 8 KB
    float2* cBuf0 = (float2*)(smem + 16384);          // 16 KB (16x128)
    float2* cBuf1 = (float2*)(smem + 32768);          // 16 KB

    int tid = threadIdx.x, tx = tid & 15, ty = tid >> 4;
    int chunk = blockIdx.x;
    int l0 = chunk * CHUNK;

    u64 acc[4][8];
#pragma unroll
    for (int i = 0; i < 4; i++)
#pragma unroll
        for (int j = 0; j < 8; j++) acc[i][j] = 0ULL;

    float2 pA[4], pX[4], pC[4];
    auto ldgX = [&](int s) {
        int p0 = s * 16;
#pragma unroll
        for (int e = 0; e < 4; e++) {
            int idx = e * 256 + tid;
            int r = idx >> 4, k = idx & 15;
            size_t g = (size_t)(l0 + r) * P_DIM + p0 + k;
            pA[e] = g_Acum[g];
            pX[e] = g_xloc[g];
            pC[e] = g_carry[chunk * P_DIM + p0 + k];
        }
    };
    auto stX = [&](int b) {
        float2* xb = b ? xBuf1 : xBuf0;
#pragma unroll
        for (int e = 0; e < 4; e++) {
            int idx = e * 256 + tid;
            int r = idx >> 4, k = idx & 15;
            float2 x;
            x.x = pA[e].x * pC[e].x - pA[e].y * pC[e].y + pX[e].x;
            x.y = pA[e].x * pC[e].y + pA[e].y * pC[e].x + pX[e].y;
            xb[r * 16 + k] = x;
        }
    };
    auto cpC = [&](int s, int b) {
        int p0 = s * 16;
        float2* cb = b ? cBuf1 : cBuf0;
#pragma unroll
        for (int e = 0; e < 4; e++) {                 // 1024 float4
            int idx = e * 256 + tid;
            int kk = idx >> 6, q = idx & 63;          // 64 float4 per row of 128 f2
            cp16(&cb[kk * H_DIM + q * 2], &g_Ct[(p0 + kk) * H_DIM + q * 2]);
        }
        cpcommit();
    };

    ldgX(0);
    cpC(0, 0);
    for (int s = 0; s < 16; s++) {
        int b = s & 1;
        stX(b);                                       // consumes regs for slice s
        if (s < 15) { ldgX(s + 1); cpC(s + 1, b ^ 1); }
        if (s < 15) cpwait<1>(); else cpwait<0>();
        __syncthreads();
        const float2* xb = b ? xBuf1 : xBuf0;
        const float2* cb = b ? cBuf1 : cBuf0;
#pragma unroll
        for (int kk = 0; kk < 16; kk++) {
            u64 xv[4], cv[8];
#pragma unroll
            for (int i = 0; i < 4; i++)
                xv[i] = *reinterpret_cast<const u64*>(&xb[(ty + 16 * i) * 16 + kk]);
#pragma unroll
            for (int j = 0; j < 8; j++)
                cv[j] = *reinterpret_cast<const u64*>(&cb[kk * H_DIM + tx + 16 * j]);
#pragma unroll
            for (int i = 0; i < 4; i++)
#pragma unroll
                for (int j = 0; j < 8; j++)
                    acc[i][j] = fma2(xv[i], cv[j], acc[i][j]);
        }
        __syncthreads();
    }

#pragma unroll
    for (int i = 0; i < 4; i++) {
        int l = l0 + ty + 16 * i;
#pragma unroll
        for (int j = 0; j < 8; j++) {
            int h = tx + 16 * j;
            float2 s = unpack2(acc[i][j]);
            out[(size_t)l * H_DIM + h] = 2.0f * (s.x - s.y) + D[h] * u[(size_t)l * H_DIM + h];
        }
    }
}

extern "C" void kernel_launch(void* const* d_in, const int* in_sizes, int n_in,
                              void* d_out, int out_size) {
    const float* u       = (const float*)d_in[0];
    const float* dts     = (const float*)d_in[1];
    const float* Lre     = (const float*)d_in[2];
    const float* Lim     = (const float*)d_in[3];
    const float* logstep = (const float*)d_in[4];
    const float* Br      = (const float*)d_in[5];
    const float* Bi      = (const float*)d_in[6];
    const float* Cr      = (const float*)d_in[7];
    const float* Ci      = (const float*)d_in[8];
    const float* D       = (const float*)d_in[9];
    float* out = (float*)d_out;

    k0_transpose<<<(H_DIM * P_DIM + 255) / 256, 256>>>(Br, Bi, Cr, Ci);
    dim3 g1(P_DIM / PTILE, L_SEQ / CHUNK);
    k1_gemm_scan<<<g1, 256>>>(u, dts, Lre, Lim, logstep);
    k2_chunkscan<<<8, 32>>>();
    k3_fixup_gemm<<<L_SEQ / CHUNK, 256>>>(u, D, out);
}